// round 5
// baseline (speedup 1.0000x reference)
#include <cuda_runtime.h>

// ---------------------------------------------------------------------------
// Residual Vector Quantization, 8 layers. R2 -> R3 (3rd submit; infra fails):
//  - j-paired FFMA2 accumulators: B smem natural (no duplication, half bytes)
//  - B row split into 4 interleaved regions -> 1-wavefront LDS.128 reads
//  - 512 threads (4 warps/SMSP), 32-k chunks (half the barriers)
// ---------------------------------------------------------------------------

namespace {
constexpr int Bb    = 16;
constexpr int Dd    = 256;
constexpr int Tt    = 4096;
constexpr int NQ    = 8;
constexpr int NBINS = 1024;
constexpr int NVEC  = Bb * Tt;        // 65536
constexpr int MTILE = 128;
constexpr int GRID_L = NVEC / MTILE;  // 512
constexpr int NTH   = 512;

constexpr int AS_STRIDE = 132;                 // A tile [k=256][m=128] padded
constexpr int AS_FLOATS = 256 * AS_STRIDE;     // 33792
constexpr int BS_ROW    = 132;                 // 128 data floats + pad
constexpr int CHUNK     = 32;                  // k rows per stage
constexpr int BS_BUF    = CHUNK * BS_ROW;      // 4224
constexpr int BS_FLOATS = 2 * BS_BUF;          // 8448 double-buffered
constexpr int SIDX_OFF  = AS_FLOATS + BS_FLOATS;   // 128 ints
constexpr int WLOSS_OFF = SIDX_OFF + 128;          // 16 floats
constexpr int SMEM_FLOATS = WLOSS_OFF + 32;
constexpr size_t SMEM_BYTES = (size_t)SMEM_FLOATS * sizeof(float);  // ~169.7 KB
}

// ---------------- device scratch --------------------------------------------
__device__ __align__(16) float g_resid[(size_t)NVEC * Dd];
__device__ __align__(16) float g_rr[NVEC];
__device__ __align__(16) float g_cc[NQ * NBINS];
__device__ __align__(16) float g_losspart[NQ * GRID_L];

// ---------------- packed f32x2 helpers --------------------------------------
__device__ __forceinline__ unsigned long long dup2(float a) {
    unsigned long long r;
    asm("mov.b64 %0, {%1, %1};" : "=l"(r) : "f"(a));
    return r;
}
__device__ __forceinline__ float2 unpack2(unsigned long long v) {
    float2 r;
    asm("mov.b64 {%0, %1}, %2;" : "=f"(r.x), "=f"(r.y) : "l"(v));
    return r;
}
__device__ __forceinline__ void fma2(unsigned long long& d,
                                     unsigned long long a,
                                     unsigned long long b) {
    asm("fma.rn.f32x2 %0, %1, %2, %0;" : "+l"(d) : "l"(a), "l"(b));
}

// ---------------- kernel: transpose x[B,D,T] -> resid[n][d] -----------------
__global__ void transpose_in_kernel(const float* __restrict__ x) {
    __shared__ float tile[32][33];
    const int b  = blockIdx.z;
    const int d0 = blockIdx.y * 32;
    const int t0 = blockIdx.x * 32;
    const int tx = threadIdx.x, ty = threadIdx.y;
    const float* xb = x + (size_t)b * Dd * Tt;
#pragma unroll
    for (int i = 0; i < 32; i += 8)
        tile[ty + i][tx] = xb[(size_t)(d0 + ty + i) * Tt + t0 + tx];
    __syncthreads();
#pragma unroll
    for (int i = 0; i < 32; i += 8) {
        const int t = t0 + ty + i;
        g_resid[(size_t)(b * Tt + t) * Dd + d0 + tx] = tile[tx][ty + i];
    }
}

// ---------------- kernel: row squared norms ---------------------------------
__global__ void rownorm_kernel() {
    const int row  = blockIdx.x * 8 + (threadIdx.x >> 5);
    const int lane = threadIdx.x & 31;
    const float* r = g_resid + (size_t)row * Dd;
    float s = 0.f;
#pragma unroll
    for (int i = 0; i < 8; i++) { float v = r[i * 32 + lane]; s = fmaf(v, v, s); }
#pragma unroll
    for (int o = 16; o; o >>= 1) s += __shfl_down_sync(0xffffffffu, s, o);
    if (!lane) g_rr[row] = s;
}

// ---------------- kernel: codebook squared norms ----------------------------
__global__ void codenorm_kernel(const float* __restrict__ cbs) {
    const int c    = blockIdx.x * 8 + (threadIdx.x >> 5);
    const int lane = threadIdx.x & 31;
    const float* r = cbs + (size_t)c * Dd;
    float s = 0.f;
#pragma unroll
    for (int i = 0; i < 8; i++) { float v = r[i * 32 + lane]; s = fmaf(v, v, s); }
#pragma unroll
    for (int o = 16; o; o >>= 1) s += __shfl_down_sync(0xffffffffu, s, o);
    if (!lane) g_cc[c] = s;
}

// ---------------- kernel: one RVQ layer -------------------------------------
__global__ __launch_bounds__(NTH, 1)
void rvq_layer_kernel(const float* __restrict__ cb,
                      int layer,
                      float* __restrict__ codes_out)
{
    extern __shared__ float sm[];
    float* As     = sm;                        // [256][132]
    float* Bs     = sm + AS_FLOATS;            // 2 x [32][132]
    float* sbest  = Bs;                        // after mainloop: [8][128]
    int*   sbestj = (int*)(Bs + 1024);         // [8][128]
    int*   sidx   = (int*)(sm + SIDX_OFF);     // [128]
    float* wloss  = sm + WLOSS_OFF;            // [16]

    const int tid = threadIdx.x;
    const int tx  = tid & 7;       // j direction: 8 threads x 16 j = 128
    const int ty  = tid >> 3;      // m direction: 64 threads x 2 m = 128
    const int n0  = blockIdx.x * MTILE;
    const float* ccL = g_cc + layer * NBINS;

    // B writer mapping: j row = tid>>2 (0..127), k octet = tid&3
    const int jw = tid >> 2;
    const int qw = tid & 3;
    // physical float position of column jw within a B row (4-region interleave)
    const int posw = ((jw >> 2) & 3) * 32 + (jw >> 4) * 4 + (jw & 3);

    // ---- A tile load: As[d][m], coalesced global reads ----
    {
        const int d  = tid & 255;
        const int mh = (tid >> 8) * 64;
        const float* rp = g_resid + (size_t)(n0 + mh) * Dd + d;
        float* ap = As + d * AS_STRIDE + mh;
#pragma unroll 8
        for (int m = 0; m < 64; m++) ap[m] = rp[(size_t)m * Dd];
    }
    float rreg[2];
    rreg[0] = g_rr[n0 + 2 * ty];
    rreg[1] = g_rr[n0 + 2 * ty + 1];

    float best[2];
    int   bestj[2];
    best[0] = best[1] = 3.402823466e38f;
    bestj[0] = bestj[1] = 0;

    __syncthreads();

    // ---- 8 j-tiles of 128 codes ----
#pragma unroll 1
    for (int jt = 0; jt < 8; jt++) {
        const int j0 = jt * 128;
        const float* cbp = cb + (size_t)(j0 + jw) * Dd + qw * 8;

        unsigned long long acc[2][8];
#pragma unroll
        for (int m = 0; m < 2; m++)
#pragma unroll
            for (int p = 0; p < 8; p++) acc[m][p] = 0ull;

        // prologue: chunk 0 -> buffer 0
        float4 va = *(const float4*)(cbp);
        float4 vb = *(const float4*)(cbp + 4);
        {
            float* dst = Bs + (qw * 8) * BS_ROW + posw;
            dst[0 * BS_ROW] = va.x; dst[1 * BS_ROW] = va.y;
            dst[2 * BS_ROW] = va.z; dst[3 * BS_ROW] = va.w;
            dst[4 * BS_ROW] = vb.x; dst[5 * BS_ROW] = vb.y;
            dst[6 * BS_ROW] = vb.z; dst[7 * BS_ROW] = vb.w;
        }
        __syncthreads();

#pragma unroll 1
        for (int c = 0; c < 8; c++) {
            if (c < 7) {
                va = *(const float4*)(cbp + (c + 1) * CHUNK);
                vb = *(const float4*)(cbp + (c + 1) * CHUNK + 4);
            }
            const float* ab = As + (c * CHUNK) * AS_STRIDE + 2 * ty;
            const float* bb = Bs + (c & 1) * BS_BUF + 4 * tx;
#pragma unroll 8
            for (int kk = 0; kk < CHUNK; kk++) {
                const float2 a = *(const float2*)(ab + kk * AS_STRIDE);
                const unsigned long long a0 = dup2(a.x);
                const unsigned long long a1 = dup2(a.y);
                const float* br = bb + kk * BS_ROW;
                const ulonglong2 c0 = *(const ulonglong2*)(br);
                const ulonglong2 c1 = *(const ulonglong2*)(br + 32);
                const ulonglong2 c2 = *(const ulonglong2*)(br + 64);
                const ulonglong2 c3 = *(const ulonglong2*)(br + 96);
                fma2(acc[0][0], a0, c0.x); fma2(acc[0][1], a0, c0.y);
                fma2(acc[0][2], a0, c1.x); fma2(acc[0][3], a0, c1.y);
                fma2(acc[0][4], a0, c2.x); fma2(acc[0][5], a0, c2.y);
                fma2(acc[0][6], a0, c3.x); fma2(acc[0][7], a0, c3.y);
                fma2(acc[1][0], a1, c0.x); fma2(acc[1][1], a1, c0.y);
                fma2(acc[1][2], a1, c1.x); fma2(acc[1][3], a1, c1.y);
                fma2(acc[1][4], a1, c2.x); fma2(acc[1][5], a1, c2.y);
                fma2(acc[1][6], a1, c3.x); fma2(acc[1][7], a1, c3.y);
            }
            if (c < 7) {
                float* dst = Bs + ((c + 1) & 1) * BS_BUF + (qw * 8) * BS_ROW + posw;
                dst[0 * BS_ROW] = va.x; dst[1 * BS_ROW] = va.y;
                dst[2 * BS_ROW] = va.z; dst[3 * BS_ROW] = va.w;
                dst[4 * BS_ROW] = vb.x; dst[5 * BS_ROW] = vb.y;
                dst[6 * BS_ROW] = vb.z; dst[7 * BS_ROW] = vb.w;
            }
            __syncthreads();
        }

        // epilogue: distances + running argmin (ascending j => first-min)
        float ccv[16];
        {
            const float4 u0 = *(const float4*)(ccL + j0 + 16 * tx);
            const float4 u1 = *(const float4*)(ccL + j0 + 16 * tx + 4);
            const float4 u2 = *(const float4*)(ccL + j0 + 16 * tx + 8);
            const float4 u3 = *(const float4*)(ccL + j0 + 16 * tx + 12);
            ccv[0]=u0.x; ccv[1]=u0.y; ccv[2]=u0.z; ccv[3]=u0.w;
            ccv[4]=u1.x; ccv[5]=u1.y; ccv[6]=u1.z; ccv[7]=u1.w;
            ccv[8]=u2.x; ccv[9]=u2.y; ccv[10]=u2.z; ccv[11]=u2.w;
            ccv[12]=u3.x; ccv[13]=u3.y; ccv[14]=u3.z; ccv[15]=u3.w;
        }
#pragma unroll
        for (int p = 0; p < 8; p++) {
            const int jb = j0 + 16 * tx + 2 * p;
#pragma unroll
            for (int m = 0; m < 2; m++) {
                const float2 d2 = unpack2(acc[m][p]);
                // mirrors jax: (rr - 2*dot) + cc
                const float dist0 = fmaf(-2.f, d2.x, rreg[m]) + ccv[2 * p];
                const float dist1 = fmaf(-2.f, d2.y, rreg[m]) + ccv[2 * p + 1];
                if (dist0 < best[m]) { best[m] = dist0; bestj[m] = jb; }
                if (dist1 < best[m]) { best[m] = dist1; bestj[m] = jb + 1; }
            }
        }
    }

    // ---- cross-thread argmin reduction (8 tx slots per m row) ----
#pragma unroll
    for (int m = 0; m < 2; m++) {
        sbest[tx * 128 + 2 * ty + m]  = best[m];
        sbestj[tx * 128 + 2 * ty + m] = bestj[m];
    }
    __syncthreads();
    if (tid < 128) {
        float bv = 3.402823466e38f;
        int   bj = 0x7fffffff;
#pragma unroll
        for (int t2 = 0; t2 < 8; t2++) {
            const float vv = sbest[t2 * 128 + tid];
            const int   jj = sbestj[t2 * 128 + tid];
            if (vv < bv || (vv == bv && jj < bj)) { bv = vv; bj = jj; }
        }
        sidx[tid] = bj;
    }
    __syncthreads();

    // ---- fused update: resid -= cb[idx]; new norms; codes; loss ----
    const int wid = tid >> 5, lane = tid & 31;
    float wl = 0.f;
    for (int m = wid; m < MTILE; m += 16) {
        const int j = sidx[m];
        const float* q = cb + (size_t)j * Dd;
        float* rout = g_resid + (size_t)(n0 + m) * Dd;
        float s = 0.f;
#pragma unroll
        for (int i = 0; i < 8; i++) {
            const int d = i * 32 + lane;
            const float rn = As[d * AS_STRIDE + m] - q[d];
            rout[d] = rn;
            s = fmaf(rn, rn, s);
        }
#pragma unroll
        for (int o = 16; o; o >>= 1) s += __shfl_down_sync(0xffffffffu, s, o);
        if (!lane) {
            g_rr[n0 + m] = s;
            wl += s;
            if (codes_out) codes_out[(size_t)layer * NVEC + n0 + m] = (float)j;
        }
    }
    if (!lane) wloss[wid] = wl;
    __syncthreads();
    if (tid == 0) {
        float t = 0.f;
#pragma unroll
        for (int w = 0; w < 16; w++) t += wloss[w];
        g_losspart[layer * GRID_L + blockIdx.x] = t;
    }
}

// ---------------- kernel: quantized = x - resid_final, + loss ---------------
__global__ void finalize_kernel(const float* __restrict__ x,
                                float* __restrict__ out,
                                float* __restrict__ loss_dst) {
    __shared__ float tile[32][33];
    const int b  = blockIdx.z;
    const int d0 = blockIdx.y * 32;
    const int t0 = blockIdx.x * 32;
    const int tx = threadIdx.x, ty = threadIdx.y;
#pragma unroll
    for (int i = 0; i < 32; i += 8)
        tile[ty + i][tx] = g_resid[(size_t)(b * Tt + t0 + ty + i) * Dd + d0 + tx];
    __syncthreads();
#pragma unroll
    for (int i = 0; i < 32; i += 8) {
        const size_t idx = (size_t)b * Dd * Tt + (size_t)(d0 + ty + i) * Tt + t0 + tx;
        out[idx] = x[idx] - tile[tx][ty + i];
    }
    if (loss_dst && blockIdx.x == 0 && blockIdx.y == 0 && blockIdx.z == 0 && ty == 0) {
        double s = 0.0;
        for (int i = tx; i < NQ * GRID_L; i += 32) s += (double)g_losspart[i];
#pragma unroll
        for (int o = 16; o; o >>= 1) s += __shfl_down_sync(0xffffffffu, s, o);
        if (tx == 0)
            *loss_dst = (float)(s / ((double)NQ * (double)NVEC * (double)Dd));
    }
}

// ---------------- launch -----------------------------------------------------
extern "C" void kernel_launch(void* const* d_in, const int* in_sizes, int n_in,
                              void* d_out, int out_size) {
    const float* x   = (const float*)d_in[0];
    const float* cbs = (const float*)d_in[1];
    float* out = (float*)d_out;

    const long long QN = (long long)Bb * Dd * Tt;
    const long long CN = (long long)NQ * Bb * Tt;
    float* codes = ((long long)out_size >= QN + CN) ? out + QN : nullptr;
    float* lossp = ((long long)out_size >= QN + CN + 1) ? out + QN + CN : nullptr;

    cudaFuncSetAttribute(rvq_layer_kernel,
                         cudaFuncAttributeMaxDynamicSharedMemorySize,
                         (int)SMEM_BYTES);

    transpose_in_kernel<<<dim3(Tt / 32, Dd / 32, Bb), dim3(32, 8)>>>(x);
    rownorm_kernel<<<NVEC / 8, 256>>>();
    codenorm_kernel<<<NQ * NBINS / 8, 256>>>(cbs);
    for (int l = 0; l < NQ; l++) {
        rvq_layer_kernel<<<GRID_L, NTH, SMEM_BYTES>>>(
            cbs + (size_t)l * NBINS * Dd, l, codes);
    }
    finalize_kernel<<<dim3(Tt / 32, Dd / 32, Bb), dim3(32, 8)>>>(x, out, lossp);
}

// round 6
// speedup vs baseline: 1.6083x; 1.6083x over previous
#include <cuda_runtime.h>

// ---------------------------------------------------------------------------
// RVQ, 8 layers. R5: phase-accurate LDS cost model.
//  CTA tile 128m x 256j, 256 threads, per-thread 16m x 8j, m-paired FFMA2.
//  LSU 192 cyc/SM/kk < FMA 256 cyc/SMSP/kk -> fma-bound, 2 warps/SMSP.
// ---------------------------------------------------------------------------

namespace {
constexpr int Bb    = 16;
constexpr int Dd    = 256;
constexpr int Tt    = 4096;
constexpr int NQ    = 8;
constexpr int NBINS = 1024;
constexpr int NVEC  = Bb * Tt;        // 65536
constexpr int MTILE = 128;
constexpr int JTILE = 256;            // j per jt iteration (4 iters)
constexpr int GRID_L = NVEC / MTILE;  // 512
constexpr int NTH   = 256;

constexpr int AS_STRIDE = 132;                  // A tile [k=256][m=128]
constexpr int AS_FLOATS = 256 * AS_STRIDE;      // 33792
constexpr int CHUNK     = 16;                   // k rows per stage
constexpr int BS_ROW    = 260;                  // 256 j + pad (16B aligned)
constexpr int BS_BUF    = CHUNK * BS_ROW;       // 4160
constexpr int BS_FLOATS = 2 * BS_BUF;           // 8320
constexpr int SIDX_OFF  = AS_FLOATS + BS_FLOATS;// 42112
constexpr int WLOSS_OFF = SIDX_OFF + 128;
constexpr int SMEM_FLOATS = WLOSS_OFF + 16;
constexpr size_t SMEM_BYTES = (size_t)SMEM_FLOATS * sizeof(float);  // ~169 KB
}

// ---------------- device scratch --------------------------------------------
__device__ __align__(16) float g_resid[(size_t)NVEC * Dd];
__device__ __align__(16) float g_rr[NVEC];
__device__ __align__(16) float g_cc[NQ * NBINS];
__device__ __align__(16) float g_losspart[NQ * GRID_L];

// ---------------- packed f32x2 helpers --------------------------------------
__device__ __forceinline__ unsigned long long dup2(float a) {
    unsigned long long r;
    asm("mov.b64 %0, {%1, %1};" : "=l"(r) : "f"(a));
    return r;
}
__device__ __forceinline__ float2 unpack2(unsigned long long v) {
    float2 r;
    asm("mov.b64 {%0, %1}, %2;" : "=f"(r.x), "=f"(r.y) : "l"(v));
    return r;
}
__device__ __forceinline__ void fma2(unsigned long long& d,
                                     unsigned long long a,
                                     unsigned long long b) {
    asm("fma.rn.f32x2 %0, %1, %2, %0;" : "+l"(d) : "l"(a), "l"(b));
}
__device__ __forceinline__ unsigned long long fma2v(unsigned long long a,
                                                    unsigned long long b,
                                                    unsigned long long c) {
    unsigned long long d;
    asm("fma.rn.f32x2 %0, %1, %2, %3;" : "=l"(d) : "l"(a), "l"(b), "l"(c));
    return d;
}
__device__ __forceinline__ unsigned long long add2(unsigned long long a,
                                                   unsigned long long b) {
    unsigned long long d;
    asm("add.rn.f32x2 %0, %1, %2;" : "=l"(d) : "l"(a), "l"(b));
    return d;
}

// ---------------- kernel: transpose x[B,D,T] -> resid[n][d] -----------------
__global__ void transpose_in_kernel(const float* __restrict__ x) {
    __shared__ float tile[32][33];
    const int b  = blockIdx.z;
    const int d0 = blockIdx.y * 32;
    const int t0 = blockIdx.x * 32;
    const int tx = threadIdx.x, ty = threadIdx.y;
    const float* xb = x + (size_t)b * Dd * Tt;
#pragma unroll
    for (int i = 0; i < 32; i += 8)
        tile[ty + i][tx] = xb[(size_t)(d0 + ty + i) * Tt + t0 + tx];
    __syncthreads();
#pragma unroll
    for (int i = 0; i < 32; i += 8) {
        const int t = t0 + ty + i;
        g_resid[(size_t)(b * Tt + t) * Dd + d0 + tx] = tile[tx][ty + i];
    }
}

// ---------------- kernel: row squared norms ---------------------------------
__global__ void rownorm_kernel() {
    const int row  = blockIdx.x * 8 + (threadIdx.x >> 5);
    const int lane = threadIdx.x & 31;
    const float* r = g_resid + (size_t)row * Dd;
    float s = 0.f;
#pragma unroll
    for (int i = 0; i < 8; i++) { float v = r[i * 32 + lane]; s = fmaf(v, v, s); }
#pragma unroll
    for (int o = 16; o; o >>= 1) s += __shfl_down_sync(0xffffffffu, s, o);
    if (!lane) g_rr[row] = s;
}

// ---------------- kernel: codebook squared norms ----------------------------
__global__ void codenorm_kernel(const float* __restrict__ cbs) {
    const int c    = blockIdx.x * 8 + (threadIdx.x >> 5);
    const int lane = threadIdx.x & 31;
    const float* r = cbs + (size_t)c * Dd;
    float s = 0.f;
#pragma unroll
    for (int i = 0; i < 8; i++) { float v = r[i * 32 + lane]; s = fmaf(v, v, s); }
#pragma unroll
    for (int o = 16; o; o >>= 1) s += __shfl_down_sync(0xffffffffu, s, o);
    if (!lane) g_cc[c] = s;
}

// ---------------- kernel: one RVQ layer -------------------------------------
__global__ __launch_bounds__(NTH, 1)
void rvq_layer_kernel(const float* __restrict__ cb,
                      int layer,
                      float* __restrict__ codes_out)
{
    extern __shared__ float sm[];
    float* As    = sm;                       // [256][132]
    float* Bs    = sm + AS_FLOATS;           // 2 x [16][260]  (Bs[k][j])
    int*   sidx  = (int*)(sm + SIDX_OFF);    // [128]
    float* wloss = sm + WLOSS_OFF;           // [8]

    const int tid  = threadIdx.x;
    const int tm   = tid >> 5;     // 0..7  : 16 m rows each (= warp id)
    const int tj   = tid & 31;     // 0..31 : 8 j each (split 4+4)
    const int n0   = blockIdx.x * MTILE;
    const float* ccL = g_cc + layer * NBINS;

    // ---- A tile: As[d][m] = resid[(n0+m)*256 + d] ----
    {
        const float* rp = g_resid + (size_t)n0 * Dd + tid;
        float* ap = As + tid * AS_STRIDE;
#pragma unroll 8
        for (int m = 0; m < MTILE; m++) ap[m] = rp[(size_t)m * Dd];
    }

    float best[16];
    int   bestj[16];
#pragma unroll
    for (int i = 0; i < 16; i++) { best[i] = 3.402823466e38f; bestj[i] = 0; }

    const unsigned long long NEG2 = dup2(-2.0f);
    __syncthreads();

    // ---- 4 j-tiles of 256 codes ----
#pragma unroll 1
    for (int jt = 0; jt < 4; jt++) {
        const int j0 = jt * JTILE;
        const float* cbp = cb + (size_t)(j0 + tid) * Dd;  // this thread's code row

        unsigned long long acc[8][8];
#pragma unroll
        for (int mp = 0; mp < 8; mp++)
#pragma unroll
            for (int p = 0; p < 8; p++) acc[mp][p] = 0ull;

        // prologue: chunk 0 -> buffer 0
        float4 v0 = *(const float4*)(cbp);
        float4 v1 = *(const float4*)(cbp + 4);
        float4 v2 = *(const float4*)(cbp + 8);
        float4 v3 = *(const float4*)(cbp + 12);
        {
            float* dst = Bs + tid;
            dst[0*BS_ROW]=v0.x; dst[1*BS_ROW]=v0.y; dst[2*BS_ROW]=v0.z; dst[3*BS_ROW]=v0.w;
            dst[4*BS_ROW]=v1.x; dst[5*BS_ROW]=v1.y; dst[6*BS_ROW]=v1.z; dst[7*BS_ROW]=v1.w;
            dst[8*BS_ROW]=v2.x; dst[9*BS_ROW]=v2.y; dst[10*BS_ROW]=v2.z; dst[11*BS_ROW]=v2.w;
            dst[12*BS_ROW]=v3.x; dst[13*BS_ROW]=v3.y; dst[14*BS_ROW]=v3.z; dst[15*BS_ROW]=v3.w;
        }
        __syncthreads();

#pragma unroll 1
        for (int c = 0; c < 16; c++) {
            if (c < 15) {
                const float* g = cbp + (c + 1) * CHUNK;
                v0 = *(const float4*)(g);
                v1 = *(const float4*)(g + 4);
                v2 = *(const float4*)(g + 8);
                v3 = *(const float4*)(g + 12);
            }
            const float* ab = As + (c * CHUNK) * AS_STRIDE + 16 * tm;
            const float* bb = Bs + (c & 1) * BS_BUF + 4 * tj;
#pragma unroll 4
            for (int kk = 0; kk < CHUNK; kk++) {
                const float* ar = ab + kk * AS_STRIDE;
                const ulonglong2 A0 = *(const ulonglong2*)(ar);
                const ulonglong2 A1 = *(const ulonglong2*)(ar + 4);
                const ulonglong2 A2 = *(const ulonglong2*)(ar + 8);
                const ulonglong2 A3 = *(const ulonglong2*)(ar + 12);
                const float* brr = bb + kk * BS_ROW;
                const float4 b0 = *(const float4*)(brr);
                const float4 b1 = *(const float4*)(brr + 128);
                unsigned long long bu[8];
                bu[0]=dup2(b0.x); bu[1]=dup2(b0.y); bu[2]=dup2(b0.z); bu[3]=dup2(b0.w);
                bu[4]=dup2(b1.x); bu[5]=dup2(b1.y); bu[6]=dup2(b1.z); bu[7]=dup2(b1.w);
#pragma unroll
                for (int p = 0; p < 8; p++) {
                    fma2(acc[0][p], A0.x, bu[p]);
                    fma2(acc[1][p], A0.y, bu[p]);
                    fma2(acc[2][p], A1.x, bu[p]);
                    fma2(acc[3][p], A1.y, bu[p]);
                    fma2(acc[4][p], A2.x, bu[p]);
                    fma2(acc[5][p], A2.y, bu[p]);
                    fma2(acc[6][p], A3.x, bu[p]);
                    fma2(acc[7][p], A3.y, bu[p]);
                }
            }
            if (c < 15) {
                float* dst = Bs + ((c + 1) & 1) * BS_BUF + tid;
                dst[0*BS_ROW]=v0.x; dst[1*BS_ROW]=v0.y; dst[2*BS_ROW]=v0.z; dst[3*BS_ROW]=v0.w;
                dst[4*BS_ROW]=v1.x; dst[5*BS_ROW]=v1.y; dst[6*BS_ROW]=v1.z; dst[7*BS_ROW]=v1.w;
                dst[8*BS_ROW]=v2.x; dst[9*BS_ROW]=v2.y; dst[10*BS_ROW]=v2.z; dst[11*BS_ROW]=v2.w;
                dst[12*BS_ROW]=v3.x; dst[13*BS_ROW]=v3.y; dst[14*BS_ROW]=v3.z; dst[15*BS_ROW]=v3.w;
            }
            __syncthreads();
        }

        // epilogue: distances + running argmin
        const float4 cc0 = *(const float4*)(ccL + j0 + 4 * tj);
        const float4 cc1 = *(const float4*)(ccL + j0 + 128 + 4 * tj);
        const float ccv[8] = {cc0.x, cc0.y, cc0.z, cc0.w, cc1.x, cc1.y, cc1.z, cc1.w};
        const ulonglong2 R0 = *(const ulonglong2*)(g_rr + n0 + 16 * tm);
        const ulonglong2 R1 = *(const ulonglong2*)(g_rr + n0 + 16 * tm + 4);
        const ulonglong2 R2 = *(const ulonglong2*)(g_rr + n0 + 16 * tm + 8);
        const ulonglong2 R3 = *(const ulonglong2*)(g_rr + n0 + 16 * tm + 12);
        const unsigned long long rrp[8] = {R0.x, R0.y, R1.x, R1.y, R2.x, R2.y, R3.x, R3.y};
#pragma unroll
        for (int p = 0; p < 8; p++) {
            const int j = j0 + 4 * tj + ((p < 4) ? p : (124 + p));  // 128 + (p-4)
            const unsigned long long ccp2 = dup2(ccv[p]);
#pragma unroll
            for (int mp = 0; mp < 8; mp++) {
                // mirrors jax: fmaf(-2, dot, rr) + cc   (packed, same per-lane rounding)
                const unsigned long long d2 = add2(fma2v(acc[mp][p], NEG2, rrp[mp]), ccp2);
                const float2 dd = unpack2(d2);
                if (dd.x < best[2*mp])   { best[2*mp]   = dd.x; bestj[2*mp]   = j; }
                if (dd.y < best[2*mp+1]) { best[2*mp+1] = dd.y; bestj[2*mp+1] = j; }
            }
        }
    }

    // ---- warp-level argmin over the 32 tj lanes (warp owns rows 16*tm..+15)
#pragma unroll
    for (int i = 0; i < 16; i++) {
        float bv = best[i];
        int   bj = bestj[i];
#pragma unroll
        for (int off = 16; off; off >>= 1) {
            const float ov = __shfl_xor_sync(0xffffffffu, bv, off);
            const int   oj = __shfl_xor_sync(0xffffffffu, bj, off);
            if (ov < bv || (ov == bv && oj < bj)) { bv = ov; bj = oj; }
        }
        if (tj == 0) sidx[16 * tm + i] = bj;
    }
    __syncthreads();

    // ---- fused update: resid -= cb[idx]; new norms; codes; loss ----
    const int wid = tid >> 5, lane = tid & 31;
    float wl = 0.f;
    for (int m = wid; m < MTILE; m += 8) {
        const int j = sidx[m];
        const float* q = cb + (size_t)j * Dd;
        float* rout = g_resid + (size_t)(n0 + m) * Dd;
        float s = 0.f;
#pragma unroll
        for (int i = 0; i < 8; i++) {
            const int d = i * 32 + lane;
            const float rn = As[d * AS_STRIDE + m] - q[d];
            rout[d] = rn;
            s = fmaf(rn, rn, s);
        }
#pragma unroll
        for (int o = 16; o; o >>= 1) s += __shfl_down_sync(0xffffffffu, s, o);
        if (!lane) {
            g_rr[n0 + m] = s;
            wl += s;
            if (codes_out) codes_out[(size_t)layer * NVEC + n0 + m] = (float)j;
        }
    }
    if (!lane) wloss[wid] = wl;
    __syncthreads();
    if (tid == 0) {
        float t = 0.f;
#pragma unroll
        for (int w = 0; w < 8; w++) t += wloss[w];
        g_losspart[layer * GRID_L + blockIdx.x] = t;
    }
}

// ---------------- kernel: quantized = x - resid_final, + loss ---------------
__global__ void finalize_kernel(const float* __restrict__ x,
                                float* __restrict__ out,
                                float* __restrict__ loss_dst) {
    __shared__ float tile[32][33];
    const int b  = blockIdx.z;
    const int d0 = blockIdx.y * 32;
    const int t0 = blockIdx.x * 32;
    const int tx = threadIdx.x, ty = threadIdx.y;
#pragma unroll
    for (int i = 0; i < 32; i += 8)
        tile[ty + i][tx] = g_resid[(size_t)(b * Tt + t0 + ty + i) * Dd + d0 + tx];
    __syncthreads();
#pragma unroll
    for (int i = 0; i < 32; i += 8) {
        const size_t idx = (size_t)b * Dd * Tt + (size_t)(d0 + ty + i) * Tt + t0 + tx;
        out[idx] = x[idx] - tile[tx][ty + i];
    }
    if (loss_dst && blockIdx.x == 0 && blockIdx.y == 0 && blockIdx.z == 0 && ty == 0) {
        double s = 0.0;
        for (int i = tx; i < NQ * GRID_L; i += 32) s += (double)g_losspart[i];
#pragma unroll
        for (int o = 16; o; o >>= 1) s += __shfl_down_sync(0xffffffffu, s, o);
        if (tx == 0)
            *loss_dst = (float)(s / ((double)NQ * (double)NVEC * (double)Dd));
    }
}

// ---------------- launch -----------------------------------------------------
extern "C" void kernel_launch(void* const* d_in, const int* in_sizes, int n_in,
                              void* d_out, int out_size) {
    const float* x   = (const float*)d_in[0];
    const float* cbs = (const float*)d_in[1];
    float* out = (float*)d_out;

    const long long QN = (long long)Bb * Dd * Tt;
    const long long CN = (long long)NQ * Bb * Tt;
    float* codes = ((long long)out_size >= QN + CN) ? out + QN : nullptr;
    float* lossp = ((long long)out_size >= QN + CN + 1) ? out + QN + CN : nullptr;

    cudaFuncSetAttribute(rvq_layer_kernel,
                         cudaFuncAttributeMaxDynamicSharedMemorySize,
                         (int)SMEM_BYTES);

    transpose_in_kernel<<<dim3(Tt / 32, Dd / 32, Bb), dim3(32, 8)>>>(x);
    rownorm_kernel<<<NVEC / 8, 256>>>();
    codenorm_kernel<<<NQ * NBINS / 8, 256>>>(cbs);
    for (int l = 0; l < NQ; l++) {
        rvq_layer_kernel<<<GRID_L, NTH, SMEM_BYTES>>>(
            cbs + (size_t)l * NBINS * Dd, l, codes);
    }
    finalize_kernel<<<dim3(Tt / 32, Dd / 32, Bb), dim3(32, 8)>>>(x, out, lossp);
}